// round 1
// baseline (speedup 1.0000x reference)
#include <cuda_runtime.h>
#include <math.h>

#define C_    384
#define HH    56
#define WW    56
#define HWSZ  3136
#define NB    16
#define EPSV  1e-5f

// Scratch for x_pw (pointwise+BN+residual result): 16*384*3136 floats = 77 MB
__device__ float g_xpw[(size_t)NB * C_ * HWSZ];

// ---------------------------------------------------------------------------
// Kernel 1: y = einsum('bchw,oc->bohw', x, pw_w); x_pw = bn(y) + x
// Batched SGEMM: per batch, W[384,384] x X[384,3136].
// Block tile 128 (O) x 64 (HW), BK=8, 256 threads, 8x4 per-thread tile.
// All dims divide exactly -> no bounds checks.
// ---------------------------------------------------------------------------
__global__ void __launch_bounds__(256) pw_bn_res_kernel(
    const float* __restrict__ x,   const float* __restrict__ w,
    const float* __restrict__ gg,  const float* __restrict__ bb,
    const float* __restrict__ mm,  const float* __restrict__ vv)
{
    __shared__ float sW[8][132];   // [k][o], padded row (528B = 33*16 -> aligned)
    __shared__ float sX[8][64];    // [k][hw]

    const int bi  = blockIdx.z;
    const int o0  = blockIdx.y * 128;
    const int hw0 = blockIdx.x * 64;
    const int tid = threadIdx.x;
    const int tx  = tid & 15;      // hw direction (16 * 4 = 64)
    const int ty  = tid >> 4;      // o  direction (16 * 8 = 128)

    float acc[8][4];
#pragma unroll
    for (int i = 0; i < 8; i++)
#pragma unroll
        for (int q = 0; q < 4; q++) acc[i][q] = 0.f;

    const float* xb = x + (size_t)bi * C_ * HWSZ;

    const int wrow = o0 + (tid >> 1);     // 128 rows, 2 threads/row
    const int wc0  = (tid & 1) * 4;       // 0 or 4
    const int xkk  = tid >> 4;            // 0..7 (only tid<128 loads X)
    const int xj4  = (tid & 15) * 4;      // 0..60

    for (int k0 = 0; k0 < C_; k0 += 8) {
        // Stage W tile (transposed into sW[k][o])
        {
            float4 wv = *(const float4*)(w + (size_t)wrow * C_ + k0 + wc0);
            const int row = tid >> 1;
            sW[wc0 + 0][row] = wv.x;
            sW[wc0 + 1][row] = wv.y;
            sW[wc0 + 2][row] = wv.z;
            sW[wc0 + 3][row] = wv.w;
        }
        // Stage X tile (hw contiguous -> coalesced float4)
        if (tid < 128) {
            float4 xv = *(const float4*)(xb + (size_t)(k0 + xkk) * HWSZ + hw0 + xj4);
            *(float4*)(&sX[xkk][xj4]) = xv;
        }
        __syncthreads();

#pragma unroll
        for (int kk = 0; kk < 8; kk++) {
            float4 A0 = *(const float4*)(&sW[kk][ty * 8]);
            float4 A1 = *(const float4*)(&sW[kk][ty * 8 + 4]);
            float4 B0 = *(const float4*)(&sX[kk][tx * 4]);
            float a[8] = {A0.x, A0.y, A0.z, A0.w, A1.x, A1.y, A1.z, A1.w};
            float bx[4] = {B0.x, B0.y, B0.z, B0.w};
#pragma unroll
            for (int i = 0; i < 8; i++)
#pragma unroll
                for (int q = 0; q < 4; q++)
                    acc[i][q] = fmaf(a[i], bx[q], acc[i][q]);
        }
        __syncthreads();
    }

    // Epilogue: BN + residual, write x_pw
#pragma unroll
    for (int i = 0; i < 8; i++) {
        const int o = o0 + ty * 8 + i;
        const float s  = gg[o] * rsqrtf(vv[o] + EPSV);
        const float sh = fmaf(-mm[o], s, bb[o]);
        const size_t base = ((size_t)bi * C_ + o) * HWSZ + hw0 + tx * 4;
        float4 xr = *(const float4*)(x + base);
        float4 ov;
        ov.x = fmaf(acc[i][0], s, sh) + xr.x;
        ov.y = fmaf(acc[i][1], s, sh) + xr.y;
        ov.z = fmaf(acc[i][2], s, sh) + xr.z;
        ov.w = fmaf(acc[i][3], s, sh) + xr.w;
        *(float4*)(g_xpw + base) = ov;
    }
}

// ---------------------------------------------------------------------------
// Kernel 2: out = gelu( bn(dwconv13x13(x_pw)) + bn(x_pw * dw1_w) )
// One block per (band of 16 rows, channel, batch). 224 threads:
// tx in [0,14) -> 4-wide output strip, ty in [0,16) -> output row.
// Register sliding window: 16 input values reused across 13 taps x 4 outputs.
// ---------------------------------------------------------------------------
__global__ void __launch_bounds__(224) dw_bn_gelu_kernel(
    const float* __restrict__ kw,
    const float* __restrict__ kg,  const float* __restrict__ kb,
    const float* __restrict__ km,  const float* __restrict__ kv,
    const float* __restrict__ d1w, const float* __restrict__ d1g,
    const float* __restrict__ d1b, const float* __restrict__ d1m,
    const float* __restrict__ d1v,
    float* __restrict__ out)
{
    __shared__ float s_in[28 * 72];   // 28 rows (16+12 halo) x 72 (68 used, padded for fp4 align)
    __shared__ float s_w[169];

    const int band = blockIdx.x;
    const int c    = blockIdx.y;
    const int bi   = blockIdx.z;
    const int tid  = threadIdx.x;
    const int r0   = band * 16;

    const float* src = g_xpw + ((size_t)bi * C_ + c) * HWSZ;

    // Load halo'd tile, zero-fill OOB (SAME padding)
    for (int idx = tid; idx < 28 * 68; idx += 224) {
        const int row = idx / 68;
        const int col = idx - row * 68;
        const int gh = r0 - 6 + row;
        const int gw = col - 6;
        float val = 0.f;
        if (gh >= 0 && gh < HH && gw >= 0 && gw < WW) val = src[gh * WW + gw];
        s_in[row * 72 + col] = val;
    }
    if (tid < 169) s_w[tid] = kw[(size_t)c * 169 + tid];
    __syncthreads();

    const int tx = tid % 14;
    const int ty = tid / 14;
    const int orow = r0 + ty;
    if (orow >= HH) return;

    const int x4 = tx * 4;
    float acc0 = 0.f, acc1 = 0.f, acc2 = 0.f, acc3 = 0.f;

#pragma unroll
    for (int i = 0; i < 13; i++) {
        const float* rp = s_in + (ty + i) * 72 + x4;   // 16B-aligned (72 and x4 mult of 4)
        float r[16];
        *(float4*)&r[0]  = *(const float4*)(rp);
        *(float4*)&r[4]  = *(const float4*)(rp + 4);
        *(float4*)&r[8]  = *(const float4*)(rp + 8);
        *(float4*)&r[12] = *(const float4*)(rp + 12);
#pragma unroll
        for (int j = 0; j < 13; j++) {
            const float wv = s_w[i * 13 + j];
            acc0 = fmaf(r[j + 0], wv, acc0);
            acc1 = fmaf(r[j + 1], wv, acc1);
            acc2 = fmaf(r[j + 2], wv, acc2);
            acc3 = fmaf(r[j + 3], wv, acc3);
        }
    }

    // Per-channel constants
    const float sk  = kg[c] * rsqrtf(kv[c] + EPSV);
    const float shk = fmaf(-km[c], sk, kb[c]);
    const float s1  = d1g[c] * rsqrtf(d1v[c] + EPSV);
    const float a2  = d1w[c] * s1;
    const float b2  = fmaf(-d1m[c], s1, d1b[c]);

    // Center values for the 1x1-depthwise branch
    const float* cp = s_in + (ty + 6) * 72 + x4 + 6;
    const float v0 = fmaf(acc0, sk, shk) + fmaf(cp[0], a2, b2);
    const float v1 = fmaf(acc1, sk, shk) + fmaf(cp[1], a2, b2);
    const float v2 = fmaf(acc2, sk, shk) + fmaf(cp[2], a2, b2);
    const float v3 = fmaf(acc3, sk, shk) + fmaf(cp[3], a2, b2);

    // Exact GELU: 0.5*v*(1+erf(v/sqrt(2)))
    const float RS2 = 0.70710678118654752f;
    float4 res;
    res.x = 0.5f * v0 * (1.f + erff(v0 * RS2));
    res.y = 0.5f * v1 * (1.f + erff(v1 * RS2));
    res.z = 0.5f * v2 * (1.f + erff(v2 * RS2));
    res.w = 0.5f * v3 * (1.f + erff(v3 * RS2));

    *(float4*)(out + ((size_t)bi * C_ + c) * HWSZ + orow * WW + x4) = res;
}

// ---------------------------------------------------------------------------
extern "C" void kernel_launch(void* const* d_in, const int* in_sizes, int n_in,
                              void* d_out, int out_size)
{
    const float* x     = (const float*)d_in[0];
    const float* pw_w  = (const float*)d_in[1];
    const float* pw_g  = (const float*)d_in[2];
    const float* pw_b  = (const float*)d_in[3];
    const float* pw_m  = (const float*)d_in[4];
    const float* pw_v  = (const float*)d_in[5];
    const float* dwk_w = (const float*)d_in[6];
    const float* dwk_g = (const float*)d_in[7];
    const float* dwk_b = (const float*)d_in[8];
    const float* dwk_m = (const float*)d_in[9];
    const float* dwk_v = (const float*)d_in[10];
    const float* dw1_w = (const float*)d_in[11];
    const float* dw1_g = (const float*)d_in[12];
    const float* dw1_b = (const float*)d_in[13];
    const float* dw1_m = (const float*)d_in[14];
    const float* dw1_v = (const float*)d_in[15];
    float* out = (float*)d_out;

    dim3 g1(HWSZ / 64, C_ / 128, NB);   // (49, 3, 16)
    pw_bn_res_kernel<<<g1, 256>>>(x, pw_w, pw_g, pw_b, pw_m, pw_v);

    dim3 g2((HH + 15) / 16, C_, NB);    // (4, 384, 16)
    dw_bn_gelu_kernel<<<g2, 224>>>(dwk_w, dwk_g, dwk_b, dwk_m, dwk_v,
                                   dw1_w, dw1_g, dw1_b, dw1_m, dw1_v, out);
}